// round 12
// baseline (speedup 1.0000x reference)
#include <cuda_runtime.h>
#include <stdint.h>

#define BATCH 4096
#define IN_DIM 512
#define HD1 1024
#define HD2 512
#define NC 50
#define NE 8
#define TM 32
#define MAXBLK 264
#define NSLOT (MAXBLK*TM)
#define NTHR 256

// ---------------- bf16 2-term split helpers ---------------------------------
__device__ __forceinline__ uint32_t pack2(float vlo, float vhi) {
    uint32_t r;
    asm("cvt.rn.satfinite.bf16x2.f32 %0, %1, %2;" : "=r"(r) : "f"(vhi), "f"(vlo));
    return r;
}
__device__ __forceinline__ float bf16lo_f(uint32_t p) { return __uint_as_float(p << 16); }
__device__ __forceinline__ float bf16hi_f(uint32_t p) { return __uint_as_float(p & 0xffff0000u); }
__device__ __forceinline__ void split2(float v0, float v1, uint32_t& h, uint32_t& l) {
    h = pack2(v0, v1);
    l = pack2(v0 - bf16lo_f(h), v1 - bf16hi_f(h));
}
__device__ __forceinline__ void mma_bf16(float c[4], const uint32_t a[4],
                                         uint32_t b0, uint32_t b1) {
    asm("mma.sync.aligned.m16n8k16.row.col.f32.bf16.bf16.f32 "
        "{%0,%1,%2,%3},{%4,%5,%6,%7},{%8,%9},{%0,%1,%2,%3};"
        : "+f"(c[0]), "+f"(c[1]), "+f"(c[2]), "+f"(c[3])
        : "r"(a[0]), "r"(a[1]), "r"(a[2]), "r"(a[3]), "r"(b0), "r"(b1));
}

#define SWX(k,m) ((k)*32 + ((m) ^ ((((k)>>1)&3)<<3)))

__device__ int   g_count[NE];
__device__ int   g_cursor[NE];
__device__ int   g_offset[NE];
__device__ int   g_slot_token[NSLOT];
__device__ float g_slot_gate[NSLOT];
__device__ int   g_topk_idx[BATCH*2];
__device__ float g_topk_val[BATCH*2];

__global__ void init_kernel() {
    int i = threadIdx.x;
    if (i < NE) { g_count[i] = 0; g_cursor[i] = 0; }
}

__global__ void zero_out_kernel(float* __restrict__ out) {
    int i = blockIdx.x * blockDim.x + threadIdx.x;
    if (i < BATCH * NC) out[i] = 0.f;
}

__global__ void router_kernel(const float* __restrict__ x,
                              const float* __restrict__ Wr,
                              const float* __restrict__ br,
                              float* __restrict__ probs_out) {
    int gwarp = (blockIdx.x * blockDim.x + threadIdx.x) >> 5;
    int lane  = threadIdx.x & 31;
    if (gwarp >= BATCH) return;
    const float* xr = x + (size_t)gwarp * IN_DIM;

    float acc[NE];
#pragma unroll
    for (int e = 0; e < NE; e++) acc[e] = 0.f;
    for (int k = lane; k < IN_DIM; k += 32) {
        float xv = xr[k];
        const float* w = Wr + (size_t)k * NE;
#pragma unroll
        for (int e = 0; e < NE; e++) acc[e] += xv * w[e];
    }
#pragma unroll
    for (int e = 0; e < NE; e++) {
#pragma unroll
        for (int o = 16; o > 0; o >>= 1)
            acc[e] += __shfl_xor_sync(0xffffffff, acc[e], o);
    }
    if (lane == 0) {
        float lg[NE], p[NE];
        float mx = -1e30f;
#pragma unroll
        for (int e = 0; e < NE; e++) { lg[e] = acc[e] + br[e]; mx = fmaxf(mx, lg[e]); }
        float s = 0.f;
#pragma unroll
        for (int e = 0; e < NE; e++) { p[e] = __expf(lg[e] - mx); s += p[e]; }
        float inv = 1.f / s;
#pragma unroll
        for (int e = 0; e < NE; e++) {
            p[e] *= inv;
            probs_out[(size_t)gwarp * NE + e] = p[e];
        }
        int i0 = 0; float v0 = p[0];
#pragma unroll
        for (int e = 1; e < NE; e++) if (p[e] > v0) { v0 = p[e]; i0 = e; }
        int i1 = -1; float v1 = -1e30f;
#pragma unroll
        for (int e = 0; e < NE; e++) if (e != i0 && p[e] > v1) { v1 = p[e]; i1 = e; }
        i1 = i1 < 0 ? 0 : i1;

        g_topk_idx[gwarp*2+0] = i0; g_topk_val[gwarp*2+0] = v0;
        g_topk_idx[gwarp*2+1] = i1; g_topk_val[gwarp*2+1] = v1;
        atomicAdd(&g_count[i0], 1);
        atomicAdd(&g_count[i1], 1);
    }
}

__global__ void offsets_kernel() {
    int o = 0;
    for (int e = 0; e < NE; e++) {
        g_offset[e] = o;
        o += (g_count[e] + TM - 1) & ~(TM - 1);
    }
}

__global__ void fill_kernel() {
    int t = blockIdx.x * blockDim.x + threadIdx.x;
    if (t >= BATCH) return;
#pragma unroll
    for (int k = 0; k < 2; k++) {
        int e = g_topk_idx[t*2+k] & 7;
        int pos = atomicAdd(&g_cursor[e], 1);
        int slot = g_offset[e] + pos;
        g_slot_token[slot] = t;
        g_slot_gate[slot]  = g_topk_val[t*2+k];
    }
}

// ---------------- fused expert MLP: bf16x2-split mma, plane-major issue -----
#define SMEM_XH   0
#define SMEM_H1S  (512*32)
#define SMEM_WSH  (SMEM_H1S + 1024*32)
#define SMEM_WSL  (SMEM_WSH + 8*520)
#define SMEM_TOTALF (SMEM_WSL + 8*520)     // 229,888 B

__global__ void __launch_bounds__(NTHR, 1)
fused_expert_kernel(const float* __restrict__ x,
                    const float* __restrict__ W1, const float* __restrict__ b1,
                    const float* __restrict__ W2, const float* __restrict__ b2,
                    const float* __restrict__ W3, const float* __restrict__ b3,
                    float* __restrict__ out) {
    extern __shared__ float sm[];
    float*    xh   = sm + SMEM_XH;
    float*    h1s  = sm + SMEM_H1S;
    uint32_t* wsbh = (uint32_t*)(sm + SMEM_WSH);
    uint32_t* wsbl = (uint32_t*)(sm + SMEM_WSL);
    float*    wsC  = sm + SMEM_WSH;

    const int tid  = threadIdx.x;
    const int w    = tid >> 5, lane = tid & 31;
    const int gid  = lane >> 2, tig = lane & 3;
    const int mh   = (w & 1) * 16;
    const int nq   = w >> 1;
    const int slot0 = blockIdx.x * TM;

    int e = -1, cnt = 0;
#pragma unroll
    for (int ee = 0; ee < NE; ee++) {
        int off = g_offset[ee];
        int pc  = (g_count[ee] + TM - 1) & ~(TM - 1);
        if (slot0 >= off && slot0 < off + pc) { e = ee; cnt = g_count[ee]; }
    }
    if (e < 0) return;
    const int rowsv = min(TM, cnt - (slot0 - g_offset[e]));

    for (int idx = tid; idx < TM * (IN_DIM/4); idx += NTHR) {
        int r  = idx / (IN_DIM/4);
        int c4 = idx % (IN_DIM/4);
        float4 v = make_float4(0.f,0.f,0.f,0.f);
        if (r < rowsv) {
            int tok = g_slot_token[slot0 + r];
            v = *(const float4*)(x + (size_t)tok * IN_DIM + c4*4);
        }
        xh[SWX(c4*4+0, r)] = v.x;
        xh[SWX(c4*4+1, r)] = v.y;
        xh[SWX(c4*4+2, r)] = v.z;
        xh[SWX(c4*4+3, r)] = v.w;
    }
    __syncthreads();

    const float* W1e = W1 + (size_t)e * IN_DIM * HD1;
    const float* W2e = W2 + (size_t)e * HD1 * HD2;
    const float* b1e = b1 + (size_t)e * HD1;
    const float* b2e = b2 + (size_t)e * HD2;

    int su_kp[4], su_n4[4];
#pragma unroll
    for (int i = 0; i < 4; i++) {
        int u = tid + i*256;
        su_kp[i] = u >> 7;
        su_n4[i] = (u & 127) * 4;
    }

    // ============ stage A: h1 = relu(x @ W1 + b1) ===========================
    for (int n0 = 0; n0 < HD1; n0 += 512) {
        float c[16][4];
#pragma unroll
        for (int t = 0; t < 16; t++)
#pragma unroll
            for (int q = 0; q < 4; q++) c[t][q] = 0.f;

        float4 pf0[4], pf1[4];
#pragma unroll
        for (int i = 0; i < 4; i++) {
            pf0[i] = *(const float4*)(W1e + (size_t)(2*su_kp[i]  ) * HD1 + n0 + su_n4[i]);
            pf1[i] = *(const float4*)(W1e + (size_t)(2*su_kp[i]+1) * HD1 + n0 + su_n4[i]);
        }

        for (int k0 = 0; k0 < IN_DIM; k0 += 16) {
            __syncthreads();
#pragma unroll
            for (int i = 0; i < 4; i++) {
                uint32_t h0,l0,h1_,l1,h2_,l2,h3,l3;
                split2(pf0[i].x, pf1[i].x, h0, l0);
                split2(pf0[i].y, pf1[i].y, h1_, l1);
                split2(pf0[i].z, pf1[i].z, h2_, l2);
                split2(pf0[i].w, pf1[i].w, h3, l3);
                uint4 hv; hv.x=h0; hv.y=h1_; hv.z=h2_; hv.w=h3;
                uint4 lv; lv.x=l0; lv.y=l1; lv.z=l2; lv.w=l3;
                *(uint4*)(wsbh + su_kp[i]*520 + su_n4[i]) = hv;
                *(uint4*)(wsbl + su_kp[i]*520 + su_n4[i]) = lv;
            }
            __syncthreads();
            if (k0 + 16 < IN_DIM) {
#pragma unroll
                for (int i = 0; i < 4; i++) {
                    pf0[i] = *(const float4*)(W1e + (size_t)(k0+16+2*su_kp[i]  ) * HD1 + n0 + su_n4[i]);
                    pf1[i] = *(const float4*)(W1e + (size_t)(k0+16+2*su_kp[i]+1) * HD1 + n0 + su_n4[i]);
                }
            }
            uint32_t ahi[4], alo[4];
            split2(xh[SWX(k0+2*tig,   mh+gid  )], xh[SWX(k0+2*tig+1, mh+gid  )], ahi[0], alo[0]);
            split2(xh[SWX(k0+2*tig,   mh+gid+8)], xh[SWX(k0+2*tig+1, mh+gid+8)], ahi[1], alo[1]);
            split2(xh[SWX(k0+2*tig+8, mh+gid  )], xh[SWX(k0+2*tig+9, mh+gid  )], ahi[2], alo[2]);
            split2(xh[SWX(k0+2*tig+8, mh+gid+8)], xh[SWX(k0+2*tig+9, mh+gid+8)], ahi[3], alo[3]);
            // plane-major passes: 16 independent accumulators per pass.
            // Per-c[t] order (hi*bh, lo*bh, hi*bl) identical to t-major version.
#pragma unroll
            for (int t = 0; t < 16; t++) {
                int nb = nq*128 + t*8 + gid;
                mma_bf16(c[t], ahi, wsbh[tig*520 + nb], wsbh[(tig+4)*520 + nb]);
            }
#pragma unroll
            for (int t = 0; t < 16; t++) {
                int nb = nq*128 + t*8 + gid;
                mma_bf16(c[t], alo, wsbh[tig*520 + nb], wsbh[(tig+4)*520 + nb]);
            }
#pragma unroll
            for (int t = 0; t < 16; t++) {
                int nb = nq*128 + t*8 + gid;
                mma_bf16(c[t], ahi, wsbl[tig*520 + nb], wsbl[(tig+4)*520 + nb]);
            }
        }
#pragma unroll
        for (int t = 0; t < 16; t++) {
            int n = n0 + nq*128 + t*8 + tig*2;
            float bv0 = b1e[n], bv1 = b1e[n+1];
            h1s[SWX(n,   mh+gid  )] = fmaxf(c[t][0] + bv0, 0.f);
            h1s[SWX(n+1, mh+gid  )] = fmaxf(c[t][1] + bv1, 0.f);
            h1s[SWX(n,   mh+gid+8)] = fmaxf(c[t][2] + bv0, 0.f);
            h1s[SWX(n+1, mh+gid+8)] = fmaxf(c[t][3] + bv1, 0.f);
        }
    }

    // ============ stage B: h2 = relu(h1 @ W2 + b2) ==========================
    {
        float c[16][4];
#pragma unroll
        for (int t = 0; t < 16; t++)
#pragma unroll
            for (int q = 0; q < 4; q++) c[t][q] = 0.f;

        float4 pf0[4], pf1[4];
#pragma unroll
        for (int i = 0; i < 4; i++) {
            pf0[i] = *(const float4*)(W2e + (size_t)(2*su_kp[i]  ) * HD2 + su_n4[i]);
            pf1[i] = *(const float4*)(W2e + (size_t)(2*su_kp[i]+1) * HD2 + su_n4[i]);
        }

        for (int k0 = 0; k0 < HD1; k0 += 16) {
            __syncthreads();
#pragma unroll
            for (int i = 0; i < 4; i++) {
                uint32_t h0,l0,h1_,l1,h2_,l2,h3,l3;
                split2(pf0[i].x, pf1[i].x, h0, l0);
                split2(pf0[i].y, pf1[i].y, h1_, l1);
                split2(pf0[i].z, pf1[i].z, h2_, l2);
                split2(pf0[i].w, pf1[i].w, h3, l3);
                uint4 hv; hv.x=h0; hv.y=h1_; hv.z=h2_; hv.w=h3;
                uint4 lv; lv.x=l0; lv.y=l1; lv.z=l2; lv.w=l3;
                *(uint4*)(wsbh + su_kp[i]*520 + su_n4[i]) = hv;
                *(uint4*)(wsbl + su_kp[i]*520 + su_n4[i]) = lv;
            }
            __syncthreads();
            if (k0 + 16 < HD1) {
#pragma unroll
                for (int i = 0; i < 4; i++) {
                    pf0[i] = *(const float4*)(W2e + (size_t)(k0+16+2*su_kp[i]  ) * HD2 + su_n4[i]);
                    pf1[i] = *(const float4*)(W2e + (size_t)(k0+16+2*su_kp[i]+1) * HD2 + su_n4[i]);
                }
            }
            uint32_t ahi[4], alo[4];
            split2(h1s[SWX(k0+2*tig,   mh+gid  )], h1s[SWX(k0+2*tig+1, mh+gid  )], ahi[0], alo[0]);
            split2(h1s[SWX(k0+2*tig,   mh+gid+8)], h1s[SWX(k0+2*tig+1, mh+gid+8)], ahi[1], alo[1]);
            split2(h1s[SWX(k0+2*tig+8, mh+gid  )], h1s[SWX(k0+2*tig+9, mh+gid  )], ahi[2], alo[2]);
            split2(h1s[SWX(k0+2*tig+8, mh+gid+8)], h1s[SWX(k0+2*tig+9, mh+gid+8)], ahi[3], alo[3]);
#pragma unroll
            for (int t = 0; t < 16; t++) {
                int nb = nq*128 + t*8 + gid;
                mma_bf16(c[t], ahi, wsbh[tig*520 + nb], wsbh[(tig+4)*520 + nb]);
            }
#pragma unroll
            for (int t = 0; t < 16; t++) {
                int nb = nq*128 + t*8 + gid;
                mma_bf16(c[t], alo, wsbh[tig*520 + nb], wsbh[(tig+4)*520 + nb]);
            }
#pragma unroll
            for (int t = 0; t < 16; t++) {
                int nb = nq*128 + t*8 + gid;
                mma_bf16(c[t], ahi, wsbl[tig*520 + nb], wsbl[(tig+4)*520 + nb]);
            }
        }
        __syncthreads();
#pragma unroll
        for (int t = 0; t < 16; t++) {
            int n = nq*128 + t*8 + tig*2;
            float bv0 = b2e[n], bv1 = b2e[n+1];
            xh[SWX(n,   mh+gid  )] = fmaxf(c[t][0] + bv0, 0.f);
            xh[SWX(n+1, mh+gid  )] = fmaxf(c[t][1] + bv1, 0.f);
            xh[SWX(n,   mh+gid+8)] = fmaxf(c[t][2] + bv0, 0.f);
            xh[SWX(n+1, mh+gid+8)] = fmaxf(c[t][3] + bv1, 0.f);
        }
    }
    __syncthreads();

    // ===== stage C =====
    const float* W3e = W3 + (size_t)e * HD2 * NC;
    float accC[7];
#pragma unroll
    for (int j = 0; j < 7; j++) accC[j] = 0.f;

    for (int k0 = 0; k0 < HD2; k0 += 64) {
        for (int idx = tid; idx < 64*NC; idx += NTHR) {
            int krr = idx / NC, cc = idx % NC;
            wsC[krr*52 + cc] = W3e[(size_t)(k0+krr)*NC + cc];
        }
        __syncthreads();
#pragma unroll
        for (int j = 0; j < 7; j++) {
            int oi = tid + j*NTHR;
            if (oi < TM*NC) {
                int r = oi / NC, cc = oi % NC;
                float s = 0.f;
#pragma unroll 8
                for (int kk = 0; kk < 64; kk++)
                    s += xh[SWX(k0+kk, r)] * wsC[kk*52 + cc];
                accC[j] += s;
            }
        }
        __syncthreads();
    }
    const float* b3e = b3 + (size_t)e * NC;
#pragma unroll
    for (int j = 0; j < 7; j++) {
        int oi = tid + j*NTHR;
        if (oi < TM*NC) {
            int r = oi / NC, cc = oi % NC;
            if (r < rowsv) {
                int tok  = g_slot_token[slot0 + r];
                float v  = g_slot_gate[slot0 + r];
                atomicAdd(&out[(size_t)tok*NC + cc], 0.5f * v * (accC[j] + b3e[cc]));
            }
        }
    }
}

// ---------------- launch ----------------------------------------------------
extern "C" void kernel_launch(void* const* d_in, const int* in_sizes, int n_in,
                              void* d_out, int out_size) {
    const float* x  = 0; const float* Wr = 0; const float* br = 0;
    const float* W1 = 0; const float* b1 = 0; const float* W2 = 0;
    const float* b2 = 0; const float* W3 = 0; const float* b3 = 0;
    int seen4096 = 0, seen4m = 0;
    for (int i = 0; i < n_in; i++) {
        const float* p = (const float*)d_in[i];
        switch (in_sizes[i]) {
            case 2097152: x  = p; break;
            case 8:       br = p; break;
            case 8192:    b1 = p; break;
            case 204800:  W3 = p; break;
            case 400:     b3 = p; break;
            case 4096:    if (seen4096++ == 0) Wr = p; else b2 = p; break;
            case 4194304: if (seen4m++   == 0) W1 = p; else W2 = p; break;
        }
    }

    float* out       = (float*)d_out;                 // [4096, 50]
    float* out_probs = out + (size_t)BATCH * NC;      // [4096, 8]

    cudaFuncSetAttribute(fused_expert_kernel,
                         cudaFuncAttributeMaxDynamicSharedMemorySize,
                         SMEM_TOTALF * (int)sizeof(float));

    init_kernel<<<1, 32>>>();
    router_kernel<<<BATCH/8, 256>>>(x, Wr, br, out_probs);
    offsets_kernel<<<1, 1>>>();
    fill_kernel<<<(BATCH + 255)/256, 256>>>();
    zero_out_kernel<<<(BATCH*NC + 255)/256, 256>>>(out);
    fused_expert_kernel<<<MAXBLK, NTHR, SMEM_TOTALF * sizeof(float)>>>(
        x, W1, b1, W2, b2, W3, b3, out);
}